// round 11
// baseline (speedup 1.0000x reference)
#include <cuda_runtime.h>
#include <cuda_bf16.h>

// durations [B=32, T=512] fp32, max_len=4096.
// repeats = (int)(d + 0.5); ends = inclusive cumsum; starts = ends - repeats
// out[b, t, j] = (starts[b,j] <= t < ends[b,j]) ? 1 : 0   -> [32, 4096, 512] fp32 (256 MiB)
//
// ONE fused kernel, write-only streaming. Single-variable change vs best (R9):
// grid 2048 -> 4096 (32 rows/block) to further shrink per-block duration and
// multi-CTA straggler spread. float4 evict-first stores, 512 threads.

#define B_BATCH 32
#define T_TEXT  512
#define MAX_LEN 4096

#define BLOCKS_PER_BATCH 128
#define ROWS_PER_BLOCK   (MAX_LEN / BLOCKS_PER_BATCH)     // 32
#define FILL_THREADS     512
#define NWARPS           (FILL_THREADS / 32)              // 16
#define QUADS_PER_ROW    (T_TEXT / 4)                     // 128
#define ROWS_PER_ITER    (FILL_THREADS / QUADS_PER_ROW)   // 4
#define ITERS            (ROWS_PER_BLOCK / ROWS_PER_ITER) // 8

__global__ __launch_bounds__(FILL_THREADS, 4)
void lr_fused_kernel(const float* __restrict__ durations,
                     float* __restrict__ out)
{
    const int b    = blockIdx.y;
    const int j    = threadIdx.x;
    const int lane = j & 31;
    const int wrp  = j >> 5;

    // s[0] = 0, s[1+j] = inclusive_cumsum(rep)[j]
    __shared__ int s[T_TEXT + 1];
    __shared__ int wsum[NWARPS];

    // --- scan prologue (redundant per block; inputs L2-resident) ---
    const float d = durations[b * T_TEXT + j];
    const int rep = (int)(d + 0.5f);   // d > 0: truncation == reference cast

    int v = rep;
    #pragma unroll
    for (int off = 1; off < 32; off <<= 1) {
        int n = __shfl_up_sync(0xFFFFFFFFu, v, off);
        if (lane >= off) v += n;
    }
    if (lane == 31) wsum[wrp] = v;
    __syncthreads();

    if (wrp == 0) {
        int wv = (lane < NWARPS) ? wsum[lane] : 0;
        #pragma unroll
        for (int off = 1; off < NWARPS; off <<= 1) {
            int n = __shfl_up_sync(0xFFFFFFFFu, wv, off);
            if (lane >= off) wv += n;
        }
        if (lane < NWARPS) wsum[lane] = wv;
        if (lane == 0) s[0] = 0;
    }
    __syncthreads();

    const int warp_off = (wrp > 0) ? wsum[wrp - 1] : 0;
    s[1 + j] = v + warp_off;
    __syncthreads();

    // --- fill mainloop: each thread owns a fixed quad of 4 tokens ---
    const int q  = j & (QUADS_PER_ROW - 1);   // quad index within row
    const int tr = j >> 7;                    // 0..3 row offset within iter
    const int j0 = q * 4;

    const int a0 = s[j0 + 0];
    const int a1 = s[j0 + 1];
    const int a2 = s[j0 + 2];
    const int a3 = s[j0 + 3];
    const int a4 = s[j0 + 4];

    const int t_base = blockIdx.x * ROWS_PER_BLOCK + tr;

    float4* row_base = (float4*)(out + ((size_t)b * MAX_LEN) * T_TEXT) + q;

    #pragma unroll
    for (int it = 0; it < ITERS; ++it) {
        const int t = t_base + it * ROWS_PER_ITER;
        float4 val;
        val.x = (a0 <= t && t < a1) ? 1.0f : 0.0f;
        val.y = (a1 <= t && t < a2) ? 1.0f : 0.0f;
        val.z = (a2 <= t && t < a3) ? 1.0f : 0.0f;
        val.w = (a3 <= t && t < a4) ? 1.0f : 0.0f;
        // evict-first streaming store: 256 MiB write-once stream
        __stcs(&row_base[(size_t)t * QUADS_PER_ROW], val);
    }
}

extern "C" void kernel_launch(void* const* d_in, const int* in_sizes, int n_in,
                              void* d_out, int out_size)
{
    const float* durations = (const float*)d_in[0];
    float* out = (float*)d_out;

    dim3 grid(BLOCKS_PER_BATCH, B_BATCH);
    lr_fused_kernel<<<grid, FILL_THREADS>>>(durations, out);
}

// round 13
// speedup vs baseline: 1.4086x; 1.4086x over previous
#include <cuda_runtime.h>
#include <cuda_bf16.h>

// durations [B=32, T=512] fp32, max_len=4096.
// repeats = (int)(d + 0.5); ends = inclusive cumsum; starts = ends - repeats
// out[b, t, j] = (starts[b,j] <= t < ends[b,j]) ? 1 : 0   -> [32, 4096, 512] fp32 (256 MiB)
//
// FINAL config (measured optimum across R4-R11 sweep):
//  - ONE fused kernel: per-block redundant warp-shuffle scan (hidden under
//    store stream), then write-only streaming fill.
//  - grid = 2048 (64 row-groups x 32 batches, 64 rows/block): prologue
//    amortized (16 store iters/thread) while blocks stay short enough to
//    load-balance. 1024 and 4096 both measured slower.
//  - float4 evict-first stores (__stcs). Policy/width proven neutral at the
//    DRAM write wall (~6.9 TB/s effective, ~87% of spec).

#define B_BATCH 32
#define T_TEXT  512
#define MAX_LEN 4096

#define BLOCKS_PER_BATCH 64
#define ROWS_PER_BLOCK   (MAX_LEN / BLOCKS_PER_BATCH)     // 64
#define FILL_THREADS     512
#define NWARPS           (FILL_THREADS / 32)              // 16
#define QUADS_PER_ROW    (T_TEXT / 4)                     // 128
#define ROWS_PER_ITER    (FILL_THREADS / QUADS_PER_ROW)   // 4
#define ITERS            (ROWS_PER_BLOCK / ROWS_PER_ITER) // 16

__global__ __launch_bounds__(FILL_THREADS, 4)
void lr_fused_kernel(const float* __restrict__ durations,
                     float* __restrict__ out)
{
    const int b    = blockIdx.y;
    const int j    = threadIdx.x;
    const int lane = j & 31;
    const int wrp  = j >> 5;

    // s[0] = 0, s[1+j] = inclusive_cumsum(rep)[j]
    __shared__ int s[T_TEXT + 1];
    __shared__ int wsum[NWARPS];

    // --- scan prologue (redundant per block; inputs L2-resident) ---
    const float d = durations[b * T_TEXT + j];
    const int rep = (int)(d + 0.5f);   // d > 0: truncation == reference cast

    int v = rep;
    #pragma unroll
    for (int off = 1; off < 32; off <<= 1) {
        int n = __shfl_up_sync(0xFFFFFFFFu, v, off);
        if (lane >= off) v += n;
    }
    if (lane == 31) wsum[wrp] = v;
    __syncthreads();

    if (wrp == 0) {
        int wv = (lane < NWARPS) ? wsum[lane] : 0;
        #pragma unroll
        for (int off = 1; off < NWARPS; off <<= 1) {
            int n = __shfl_up_sync(0xFFFFFFFFu, wv, off);
            if (lane >= off) wv += n;
        }
        if (lane < NWARPS) wsum[lane] = wv;
        if (lane == 0) s[0] = 0;
    }
    __syncthreads();

    const int warp_off = (wrp > 0) ? wsum[wrp - 1] : 0;
    s[1 + j] = v + warp_off;
    __syncthreads();

    // --- fill mainloop: each thread owns a fixed quad of 4 tokens ---
    const int q  = j & (QUADS_PER_ROW - 1);   // quad index within row
    const int tr = j >> 7;                    // 0..3 row offset within iter
    const int j0 = q * 4;

    const int a0 = s[j0 + 0];
    const int a1 = s[j0 + 1];
    const int a2 = s[j0 + 2];
    const int a3 = s[j0 + 3];
    const int a4 = s[j0 + 4];

    const int t_base = blockIdx.x * ROWS_PER_BLOCK + tr;

    float4* row_base = (float4*)(out + ((size_t)b * MAX_LEN) * T_TEXT) + q;

    #pragma unroll
    for (int it = 0; it < ITERS; ++it) {
        const int t = t_base + it * ROWS_PER_ITER;
        float4 val;
        val.x = (a0 <= t && t < a1) ? 1.0f : 0.0f;
        val.y = (a1 <= t && t < a2) ? 1.0f : 0.0f;
        val.z = (a2 <= t && t < a3) ? 1.0f : 0.0f;
        val.w = (a3 <= t && t < a4) ? 1.0f : 0.0f;
        // evict-first streaming store: 256 MiB write-once stream
        __stcs(&row_base[(size_t)t * QUADS_PER_ROW], val);
    }
}

extern "C" void kernel_launch(void* const* d_in, const int* in_sizes, int n_in,
                              void* d_out, int out_size)
{
    const float* durations = (const float*)d_in[0];
    float* out = (float*)d_out;

    dim3 grid(BLOCKS_PER_BATCH, B_BATCH);
    lr_fused_kernel<<<grid, FILL_THREADS>>>(durations, out);
}

// round 14
// speedup vs baseline: 1.4367x; 1.0200x over previous
#include <cuda_runtime.h>
#include <cuda_bf16.h>

// durations [B=32, T=512] fp32, max_len=4096.
// repeats = (int)(d + 0.5); ends = inclusive cumsum; starts = ends - repeats
// out[b, t, j] = (starts[b,j] <= t < ends[b,j]) ? 1 : 0   -> [32, 4096, 512] fp32 (256 MiB)
//
// Variant vs best (R13): 1024-thread blocks, 1024 blocks (128 rows/block).
// Per-thread store work (16 float4 iters), resident warps/SM, and wave count
// are IDENTICAL to the 512thr/2048blk optimum — but chip-wide scan-prologue
// count halves (1024 scans instead of 2048).

#define B_BATCH 32
#define T_TEXT  512
#define MAX_LEN 4096

#define BLOCKS_PER_BATCH 32
#define ROWS_PER_BLOCK   (MAX_LEN / BLOCKS_PER_BATCH)     // 128
#define FILL_THREADS     1024
#define NWARPS_SCAN      (T_TEXT / 32)                    // 16 (warps doing scan)
#define QUADS_PER_ROW    (T_TEXT / 4)                     // 128
#define ROWS_PER_ITER    (FILL_THREADS / QUADS_PER_ROW)   // 8
#define ITERS            (ROWS_PER_BLOCK / ROWS_PER_ITER) // 16

__global__ __launch_bounds__(FILL_THREADS, 2)
void lr_fused_kernel(const float* __restrict__ durations,
                     float* __restrict__ out)
{
    const int b    = blockIdx.y;
    const int j    = threadIdx.x;
    const int lane = j & 31;
    const int wrp  = j >> 5;

    // s[0] = 0, s[1+k] = inclusive_cumsum(rep)[k]
    __shared__ int s[T_TEXT + 1];
    __shared__ int wsum[NWARPS_SCAN];

    // --- scan prologue: warps 0..15 only (512 scan lanes) ---
    if (j < T_TEXT) {
        const float d = durations[b * T_TEXT + j];
        const int rep = (int)(d + 0.5f);   // d > 0: truncation == reference cast

        int v = rep;
        #pragma unroll
        for (int off = 1; off < 32; off <<= 1) {
            int n = __shfl_up_sync(0xFFFFFFFFu, v, off);
            if (lane >= off) v += n;
        }
        if (lane == 31) wsum[wrp] = v;
        __syncthreads();

        if (wrp == 0) {
            int wv = (lane < NWARPS_SCAN) ? wsum[lane] : 0;
            #pragma unroll
            for (int off = 1; off < NWARPS_SCAN; off <<= 1) {
                int n = __shfl_up_sync(0xFFFFFFFFu, wv, off);
                if (lane >= off) wv += n;
            }
            if (lane < NWARPS_SCAN) wsum[lane] = wv;
            if (lane == 0) s[0] = 0;
        }
        __syncthreads();

        const int warp_off = (wrp > 0) ? wsum[wrp - 1] : 0;
        s[1 + j] = v + warp_off;
    } else {
        // non-scan warps must participate in the two barriers above
        __syncthreads();
        __syncthreads();
    }
    __syncthreads();

    // --- fill mainloop: each thread owns a fixed quad of 4 tokens ---
    const int q  = j & (QUADS_PER_ROW - 1);   // quad index within row
    const int tr = j >> 7;                    // 0..7 row offset within iter
    const int j0 = q * 4;

    const int a0 = s[j0 + 0];
    const int a1 = s[j0 + 1];
    const int a2 = s[j0 + 2];
    const int a3 = s[j0 + 3];
    const int a4 = s[j0 + 4];

    const int t_base = blockIdx.x * ROWS_PER_BLOCK + tr;

    float4* row_base = (float4*)(out + ((size_t)b * MAX_LEN) * T_TEXT) + q;

    #pragma unroll
    for (int it = 0; it < ITERS; ++it) {
        const int t = t_base + it * ROWS_PER_ITER;
        float4 val;
        val.x = (a0 <= t && t < a1) ? 1.0f : 0.0f;
        val.y = (a1 <= t && t < a2) ? 1.0f : 0.0f;
        val.z = (a2 <= t && t < a3) ? 1.0f : 0.0f;
        val.w = (a3 <= t && t < a4) ? 1.0f : 0.0f;
        // evict-first streaming store: 256 MiB write-once stream
        __stcs(&row_base[(size_t)t * QUADS_PER_ROW], val);
    }
}

extern "C" void kernel_launch(void* const* d_in, const int* in_sizes, int n_in,
                              void* d_out, int out_size)
{
    const float* durations = (const float*)d_in[0];
    float* out = (float*)d_out;

    dim3 grid(BLOCKS_PER_BATCH, B_BATCH);
    lr_fused_kernel<<<grid, FILL_THREADS>>>(durations, out);
}

// round 15
// speedup vs baseline: 1.4422x; 1.0039x over previous
#include <cuda_runtime.h>
#include <cuda_bf16.h>

// durations [B=32, T=512] fp32, max_len=4096.
// repeats = (int)(d + 0.5); ends = inclusive cumsum; starts = ends - repeats
// out[b, t, j] = (starts[b,j] <= t < ends[b,j]) ? 1 : 0   -> [32, 4096, 512] fp32 (256 MiB)
//
// FINAL config (confirmation re-bench of session best, R14):
//  - ONE fused kernel: per-block redundant warp-shuffle scan, then
//    write-only streaming fill (every element written exactly once).
//  - 1024-thread blocks, grid = 1024 (32 row-groups x 32 batches,
//    128 rows/block): same per-thread store work and residency as the
//    512thr/2048blk config but half the chip-wide scan prologues.
//  - float4 evict-first stores (__stcs); policy/width measured neutral at
//    the DRAM write wall (~6.9 TB/s effective, ~87% of HBM3e spec).

#define B_BATCH 32
#define T_TEXT  512
#define MAX_LEN 4096

#define BLOCKS_PER_BATCH 32
#define ROWS_PER_BLOCK   (MAX_LEN / BLOCKS_PER_BATCH)     // 128
#define FILL_THREADS     1024
#define NWARPS_SCAN      (T_TEXT / 32)                    // 16 (warps doing scan)
#define QUADS_PER_ROW    (T_TEXT / 4)                     // 128
#define ROWS_PER_ITER    (FILL_THREADS / QUADS_PER_ROW)   // 8
#define ITERS            (ROWS_PER_BLOCK / ROWS_PER_ITER) // 16

__global__ __launch_bounds__(FILL_THREADS, 2)
void lr_fused_kernel(const float* __restrict__ durations,
                     float* __restrict__ out)
{
    const int b    = blockIdx.y;
    const int j    = threadIdx.x;
    const int lane = j & 31;
    const int wrp  = j >> 5;

    // s[0] = 0, s[1+k] = inclusive_cumsum(rep)[k]
    __shared__ int s[T_TEXT + 1];
    __shared__ int wsum[NWARPS_SCAN];

    // --- scan prologue: warps 0..15 only (512 scan lanes) ---
    if (j < T_TEXT) {
        const float d = durations[b * T_TEXT + j];
        const int rep = (int)(d + 0.5f);   // d > 0: truncation == reference cast

        int v = rep;
        #pragma unroll
        for (int off = 1; off < 32; off <<= 1) {
            int n = __shfl_up_sync(0xFFFFFFFFu, v, off);
            if (lane >= off) v += n;
        }
        if (lane == 31) wsum[wrp] = v;
        __syncthreads();

        if (wrp == 0) {
            int wv = (lane < NWARPS_SCAN) ? wsum[lane] : 0;
            #pragma unroll
            for (int off = 1; off < NWARPS_SCAN; off <<= 1) {
                int n = __shfl_up_sync(0xFFFFFFFFu, wv, off);
                if (lane >= off) wv += n;
            }
            if (lane < NWARPS_SCAN) wsum[lane] = wv;
            if (lane == 0) s[0] = 0;
        }
        __syncthreads();

        const int warp_off = (wrp > 0) ? wsum[wrp - 1] : 0;
        s[1 + j] = v + warp_off;
    } else {
        // non-scan warps must participate in the two barriers above
        __syncthreads();
        __syncthreads();
    }
    __syncthreads();

    // --- fill mainloop: each thread owns a fixed quad of 4 tokens ---
    const int q  = j & (QUADS_PER_ROW - 1);   // quad index within row
    const int tr = j >> 7;                    // 0..7 row offset within iter
    const int j0 = q * 4;

    const int a0 = s[j0 + 0];
    const int a1 = s[j0 + 1];
    const int a2 = s[j0 + 2];
    const int a3 = s[j0 + 3];
    const int a4 = s[j0 + 4];

    const int t_base = blockIdx.x * ROWS_PER_BLOCK + tr;

    float4* row_base = (float4*)(out + ((size_t)b * MAX_LEN) * T_TEXT) + q;

    #pragma unroll
    for (int it = 0; it < ITERS; ++it) {
        const int t = t_base + it * ROWS_PER_ITER;
        float4 val;
        val.x = (a0 <= t && t < a1) ? 1.0f : 0.0f;
        val.y = (a1 <= t && t < a2) ? 1.0f : 0.0f;
        val.z = (a2 <= t && t < a3) ? 1.0f : 0.0f;
        val.w = (a3 <= t && t < a4) ? 1.0f : 0.0f;
        // evict-first streaming store: 256 MiB write-once stream
        __stcs(&row_base[(size_t)t * QUADS_PER_ROW], val);
    }
}

extern "C" void kernel_launch(void* const* d_in, const int* in_sizes, int n_in,
                              void* d_out, int out_size)
{
    const float* durations = (const float*)d_in[0];
    float* out = (float*)d_out;

    dim3 grid(BLOCKS_PER_BATCH, B_BATCH);
    lr_fused_kernel<<<grid, FILL_THREADS>>>(durations, out);
}